// round 17
// baseline (speedup 1.0000x reference)
#include <cuda_runtime.h>
#include <cuda_fp16.h>
#include <math.h>
#include <stdint.h>

#define NG 50000
#define NS 10000
#define EG 800000
#define ES 160000

// ---- scratch layout (float-indexed; half arrays alias 2 halfs per float) ----
static const size_t H0_G  = 0;         // NG*64 halfs = 1.6M floats
static const size_t H0_S  = 1600000;   // NS*64 halfs
static const size_t AGG_G = 2000000;   // NG*128 halfs max
static const size_t AGG_S = 5200000;
static const size_t X1_G  = 6000000;   // NG*128 halfs
static const size_t X1_S  = 9200000;
static const size_t X2_G  = 10000000;  // NG*256 halfs
static const size_t X2_S  = 16400000;
static const size_t X3_G  = 18000000;  // NG*384 halfs
static const size_t X3_S  = 27600000;
static const size_t POOL  = 30000000;  // 2*8*192 floats
static const size_t CNTO  = 30003072;  // 16 floats
static const size_t DEG_G = 30003104;  // ints
static const size_t DEG_S = 30053105;
static const size_t PTR_G = 30063106;
static const size_t PTR_S = 30113107;
static const size_t FILL_G= 30123108;
static const size_t FILL_S= 30173108;
static const size_t SS_G  = 30183108;
static const size_t SS_S  = 30983108;
static const size_t BS_G  = 31143108;
static const size_t BS_S  = 31143308;
__device__ float d_scratch[31143360];

__device__ __forceinline__ void ldsm_x4(uint32_t& r0, uint32_t& r1, uint32_t& r2, uint32_t& r3, uint32_t addr) {
    asm volatile("ldmatrix.sync.aligned.m8n8.x4.shared.b16 {%0,%1,%2,%3}, [%4];"
                 : "=r"(r0), "=r"(r1), "=r"(r2), "=r"(r3) : "r"(addr));
}

// ---------------- init: zero (pool/cnt/deg) + fp32->fp16 input convert, one launch ----------------
__global__ void init_k(float* __restrict__ zbase, int nz4,
                       const float* __restrict__ x0, __half* __restrict__ h0, int n2a,
                       const float* __restrict__ x1, __half* __restrict__ h1, int n2b) {
    int i = blockIdx.x * 256 + threadIdx.x;
    if (i < nz4) {
        ((float4*)zbase)[i] = make_float4(0.f, 0.f, 0.f, 0.f);
        return;
    }
    int j = i - nz4;
    if (j < n2a) {
        float2 v = *(const float2*)(x0 + 2 * (size_t)j);
        *(__half2*)(h0 + 2 * (size_t)j) = __floats2half2_rn(v.x, v.y);
    } else {
        int k = j - n2a;
        if (k >= n2b) return;
        float2 v = *(const float2*)(x1 + 2 * (size_t)k);
        *(__half2*)(h1 + 2 * (size_t)k) = __floats2half2_rn(v.x, v.y);
    }
}

// ---------------- CSR build ----------------
__global__ void hist_c(const int* __restrict__ ei0, int E0, int* __restrict__ deg0,
                       const int* __restrict__ ei1, int E1, int* __restrict__ deg1) {
    int i = blockIdx.x * 256 + threadIdx.x;
    if (i < E0) atomicAdd(&deg0[ei0[E0 + i]], 1);
    else {
        int j = i - E0;
        if (j < E1) atomicAdd(&deg1[ei1[E1 + j]], 1);
    }
}

__global__ void scan_blk(const int* __restrict__ dga, int* __restrict__ pta,
                         int* __restrict__ bsa, int Na, int nba,
                         const int* __restrict__ dgb, int* __restrict__ ptb,
                         int* __restrict__ bsb, int Nb) {
    const int* deg; int* ptr; int* bs; int N, b;
    if ((int)blockIdx.x < nba) { deg = dga; ptr = pta; bs = bsa; N = Na; b = blockIdx.x; }
    else                        { deg = dgb; ptr = ptb; bs = bsb; N = Nb; b = blockIdx.x - nba; }
    __shared__ int s[256];
    int t = threadIdx.x, i = b * 256 + t;
    int v = (i < N) ? deg[i] : 0;
    s[t] = v;
    __syncthreads();
    #pragma unroll
    for (int off = 1; off < 256; off <<= 1) {
        int u = (t >= off) ? s[t - off] : 0;
        __syncthreads();
        s[t] += u;
        __syncthreads();
    }
    if (i < N) ptr[i] = s[t] - v;
    if (t == 255) bs[b] = s[255];
}

// merged top-scan + offset-apply: every block redundantly scans both block-sum arrays in smem
__global__ void scan_fin(int* __restrict__ pta, int* __restrict__ fla,
                         const int* __restrict__ bsa, int Na, int nba,
                         int* __restrict__ ptb, int* __restrict__ flb,
                         const int* __restrict__ bsb, int Nb, int nbb) {
    __shared__ int sg[256], sb[256];
    __shared__ int totg, totb;
    int t = threadIdx.x;
    int vg = (t < nba) ? bsa[t] : 0;
    int vb = (t < nbb) ? bsb[t] : 0;
    sg[t] = vg; sb[t] = vb;
    __syncthreads();
    #pragma unroll
    for (int off = 1; off < 256; off <<= 1) {
        int ug = (t >= off) ? sg[t - off] : 0;
        int ub = (t >= off) ? sb[t - off] : 0;
        __syncthreads();
        sg[t] += ug; sb[t] += ub;
        __syncthreads();
    }
    if (t == 255) { totg = sg[nba - 1]; totb = sb[nbb - 1]; }
    int eg = sg[t] - vg, eb = sb[t] - vb;
    __syncthreads();
    sg[t] = eg; sb[t] = eb;
    __syncthreads();

    int idx = blockIdx.x * 256 + t;
    if (idx <= Na) {
        if (idx < Na) {
            int p = pta[idx] + sg[idx >> 8];
            pta[idx] = p;
            fla[idx] = p;
        } else {
            pta[Na] = totg;
        }
    } else {
        int i = idx - Na - 1;
        if (i > Nb) return;
        if (i < Nb) {
            int p = ptb[i] + sb[i >> 8];
            ptb[i] = p;
            flb[i] = p;
        } else {
            ptb[Nb] = totb;
        }
    }
}

__global__ void fill_c(const int* __restrict__ ei0, int E0, int* __restrict__ fill0, int* __restrict__ ss0,
                       const int* __restrict__ ei1, int E1, int* __restrict__ fill1, int* __restrict__ ss1) {
    int i = blockIdx.x * 256 + threadIdx.x;
    if (i < E0) {
        int dst = ei0[E0 + i];
        int p = atomicAdd(&fill0[dst], 1);
        ss0[p] = ei0[i];
    } else {
        int j = i - E0;
        if (j >= E1) return;
        int dst = ei1[E1 + j];
        int p = atomicAdd(&fill1[dst], 1);
        ss1[p] = ei1[j];
    }
}

// ---------------- CSR gather with warp-segment shuffle index broadcast ----------------
// G = 2^SHIFT lanes per node; each lane owns 8 half-cols. Per chunk of G edges: lane g
// loads ss[e+g], then a width-G shfl j-loop broadcasts indices; per-column accumulation
// order is identical to the serial version.
template<int C, int SHIFT>
__global__ void gather_h(const __half* __restrict__ x0, const int* __restrict__ ptr0,
                         const int* __restrict__ ss0, __half* __restrict__ agg0, int N0,
                         const __half* __restrict__ x1, const int* __restrict__ ptr1,
                         const int* __restrict__ ss1, __half* __restrict__ agg1, int N1) {
    const int G = 1 << SHIFT;
    int idx = blockIdx.x * 256 + threadIdx.x;
    const __half* x; const int* ptr; const int* ss; __half* agg; int i;
    bool valid = true;
    int t0 = N0 << SHIFT;
    if (idx < t0) { x = x0; ptr = ptr0; ss = ss0; agg = agg0; i = idx; }
    else {
        i = idx - t0;
        x = x1; ptr = ptr1; ss = ss1; agg = agg1;
        if (i >= (N1 << SHIFT)) { valid = false; i = 0; }
    }
    int n = i >> SHIFT;
    int g = i & (G - 1);
    int q = g << 3;
    int lane = threadIdx.x & 31;
    unsigned gmask = (G == 32) ? 0xffffffffu : (((1u << G) - 1u) << (lane & ~(G - 1)));
    int e0 = 0, e1 = 0;
    if (valid) { e0 = ptr[n]; e1 = ptr[n + 1]; }
    float2 a[4];
    #pragma unroll
    for (int j = 0; j < 4; j++) a[j] = make_float2(0.f, 0.f);
    for (int e = e0; e < e1; e += G) {
        int sv = (e + g < e1) ? __ldg(ss + e + g) : 0;
        int lim = min(G, e1 - e);
        for (int j = 0; j < lim; j++) {
            int s = __shfl_sync(gmask, sv, j, G);
            uint4 v = __ldg((const uint4*)(x + (size_t)s * C + q));
            const __half2* hv = (const __half2*)&v;
            #pragma unroll
            for (int r = 0; r < 4; r++) {
                float2 f = __half22float2(hv[r]);
                a[r].x += f.x; a[r].y += f.y;
            }
        }
    }
    if (valid) {
        uint4 r;
        __half2* hr = (__half2*)&r;
        #pragma unroll
        for (int j = 0; j < 4; j++) hr[j] = __floats2half2_rn(a[j].x, a[j].y);
        *(uint4*)(agg + (size_t)n * C + q) = r;
    }
}

// layer-3 gather: x3[n,192+col] += sum x3[src,col]. G=8 lanes per node, each lane owns
// 3 uint4 chunks (cols g*8, 64+g*8, 128+g*8). Same per-column accumulation order.
__global__ void gather3_h(const int* __restrict__ ptr0, const int* __restrict__ ss0,
                          __half* __restrict__ x30, int N0,
                          const int* __restrict__ ptr1, const int* __restrict__ ss1,
                          __half* __restrict__ x31, int N1) {
    int idx = blockIdx.x * 256 + threadIdx.x;
    const int* ptr; const int* ss; __half* x3; int i;
    bool valid = true;
    int t0 = N0 * 8;
    if (idx < t0) { ptr = ptr0; ss = ss0; x3 = x30; i = idx; }
    else {
        i = idx - t0;
        ptr = ptr1; ss = ss1; x3 = x31;
        if (i >= N1 * 8) { valid = false; i = 0; }
    }
    int n = i >> 3;
    int g = i & 7;
    int q = g << 3;
    int lane = threadIdx.x & 31;
    unsigned gmask = 0xFFu << (lane & ~7);
    int e0 = 0, e1 = 0;
    if (valid) { e0 = ptr[n]; e1 = ptr[n + 1]; }
    float2 a[3][4];
    if (valid) {
        #pragma unroll
        for (int r = 0; r < 3; r++) {
            uint4 v = *(const uint4*)(x3 + (size_t)n * 384 + 192 + r * 64 + q);
            const __half2* hv = (const __half2*)&v;
            #pragma unroll
            for (int j = 0; j < 4; j++) a[r][j] = __half22float2(hv[j]);
        }
    } else {
        #pragma unroll
        for (int r = 0; r < 3; r++)
            #pragma unroll
            for (int j = 0; j < 4; j++) a[r][j] = make_float2(0.f, 0.f);
    }
    for (int e = e0; e < e1; e += 8) {
        int sv = (e + g < e1) ? __ldg(ss + e + g) : 0;
        int lim = min(8, e1 - e);
        for (int j = 0; j < lim; j++) {
            int s = __shfl_sync(gmask, sv, j, 8);
            const __half* base = x3 + (size_t)s * 384 + q;
            #pragma unroll
            for (int r = 0; r < 3; r++) {
                uint4 v = __ldg((const uint4*)(base + r * 64));
                const __half2* hv = (const __half2*)&v;
                #pragma unroll
                for (int k = 0; k < 4; k++) {
                    float2 f = __half22float2(hv[k]);
                    a[r][k].x += f.x; a[r][k].y += f.y;
                }
            }
        }
    }
    if (valid) {
        #pragma unroll
        for (int r = 0; r < 3; r++) {
            uint4 rv;
            __half2* hr = (__half2*)&rv;
            #pragma unroll
            for (int j = 0; j < 4; j++) hr[j] = __floats2half2_rn(a[r][j].x, a[r][j].y);
            *(uint4*)(x3 + (size_t)n * 384 + 192 + r * 64 + q) = rv;
        }
    }
}

// ---------------- fp16 GEMM (m16n8k16, fp32 accum): compile-time shapes, resident n-major B,
// reg-double-buffered A. MODE 0: out = ELU([A1|A2(k>=C)] @ [Wr|Wn]^T + bias)
// MODE 1: layer 3 — B row n = (n<192 ? W3r[n] : W3n[n-192]), bias = (n<192 ? 0 : B3[n-192])
template<int C, int K, int O, int MODE>
__global__ void gemm_h(const __half* __restrict__ A1g, const __half* __restrict__ A2g,
                       const float* __restrict__ Wrg, const float* __restrict__ Wng,
                       const float* __restrict__ bgg, __half* __restrict__ outg, int N0,
                       const __half* __restrict__ A1s, const __half* __restrict__ A2s,
                       const float* __restrict__ Wrs, const float* __restrict__ Wns,
                       const float* __restrict__ bss, __half* __restrict__ outs, int N1,
                       int blocks0) {
    extern __shared__ __half smh[];
    const int BSH = K + 8;
    __half* Bp = smh;                  // [64][K+8]
    __half* Ap = smh + 64 * BSH;       // [2][128][40]

    const __half *A1, *A2; const float *Wr, *Wn, *bias; __half* out; int Nrows, m0;
    int by = blockIdx.y;
    if (by < blocks0) { A1 = A1g; A2 = A2g; Wr = Wrg; Wn = Wng; bias = bgg; out = outg; Nrows = N0; m0 = by * 128; }
    else              { A1 = A1s; A2 = A2s; Wr = Wrs; Wn = Wns; bias = bss; out = outs; Nrows = N1; m0 = (by - blocks0) * 128; }
    int n0 = blockIdx.x * 64;
    int tid = threadIdx.x, warp = tid >> 5, lane = tid & 31;
    int wm = warp >> 2, wn = warp & 3, lr = lane >> 2, lc = lane & 3;

    const int KQ = K / 4;
    #pragma unroll 4
    for (int i = tid; i < 64 * KQ; i += 256) {
        int n = i / KQ, k = (i - n * KQ) << 2;
        int ng = n0 + n;
        const float* src;
        if (MODE == 0) src = (k < C) ? (Wr + (size_t)ng * C + k) : (Wn + (size_t)ng * C + (k - C));
        else           src = (ng < 192) ? (Wr + (size_t)ng * 256 + k) : (Wn + (size_t)(ng - 192) * 256 + k);
        float4 v = *(const float4*)src;
        __half2* dst = (__half2*)&Bp[n * BSH + k];
        dst[0] = __floats2half2_rn(v.x, v.y);
        dst[1] = __floats2half2_rn(v.z, v.w);
    }

    uint32_t b_base = (uint32_t)__cvta_generic_to_shared(Bp);
    uint32_t a_base0 = (uint32_t)__cvta_generic_to_shared(Ap);
    uint32_t a_base1 = a_base0 + 128 * 40 * 2;
    int arow = lane & 15, acolo = (lane >> 4) << 3;
    int browx = (lane & 7) + ((lane >> 4) << 3);
    int bcolx = ((lane >> 3) & 1) << 3;

    float acc[4][2][4] = {};
    int am = tid >> 2, akc = (tid & 3) << 3;
    int gm0 = m0 + am, gm1 = m0 + am + 64;
    uint4 st0, st1;
    const uint4 Z = make_uint4(0, 0, 0, 0);
    st0 = (gm0 < Nrows) ? *(const uint4*)(A1 + (size_t)gm0 * C + akc) : Z;
    st1 = (gm1 < Nrows) ? *(const uint4*)(A1 + (size_t)gm1 * C + akc) : Z;

    const int ITERS = K / 32;
    #pragma unroll
    for (int it = 0; it < ITERS; it++) {
        __half* Ab = Ap + (it & 1) * (128 * 40);
        uint32_t a_base = (it & 1) ? a_base1 : a_base0;
        *(uint4*)&Ab[am * 40 + akc]        = st0;
        *(uint4*)&Ab[(am + 64) * 40 + akc] = st1;
        __syncthreads();
        if (it + 1 < ITERS) {
            const int k0 = (it + 1) << 5;
            const __half* A = (k0 < C) ? A1 : A2;
            const int col0 = (k0 < C) ? k0 : (k0 - C);
            st0 = (gm0 < Nrows) ? *(const uint4*)(A + (size_t)gm0 * C + col0 + akc) : Z;
            st1 = (gm1 < Nrows) ? *(const uint4*)(A + (size_t)gm1 * C + col0 + akc) : Z;
        }
        const int kbase = it << 5;
        #pragma unroll
        for (int ks = 0; ks < 2; ks++) {
            const int kq_ = ks << 4;
            uint32_t af[4][4];
            #pragma unroll
            for (int mt = 0; mt < 4; mt++) {
                int mb = wm * 64 + mt * 16;
                uint32_t addr = a_base + (uint32_t)(((mb + arow) * 40 + kq_ + acolo) << 1);
                ldsm_x4(af[mt][0], af[mt][1], af[mt][2], af[mt][3], addr);
            }
            uint32_t bf[2][2];
            {
                int nb = wn * 16;
                uint32_t addr = b_base + (uint32_t)(((nb + browx) * BSH + kbase + kq_ + bcolx) << 1);
                ldsm_x4(bf[0][0], bf[0][1], bf[1][0], bf[1][1], addr);
            }
            #pragma unroll
            for (int nt = 0; nt < 2; nt++) {
                #pragma unroll
                for (int mt = 0; mt < 4; mt++) {
                    asm volatile(
                        "mma.sync.aligned.m16n8k16.row.col.f32.f16.f16.f32 "
                        "{%0,%1,%2,%3}, {%4,%5,%6,%7}, {%8,%9}, {%0,%1,%2,%3};"
                        : "+f"(acc[mt][nt][0]), "+f"(acc[mt][nt][1]),
                          "+f"(acc[mt][nt][2]), "+f"(acc[mt][nt][3])
                        : "r"(af[mt][0]), "r"(af[mt][1]), "r"(af[mt][2]), "r"(af[mt][3]),
                          "r"(bf[nt][0]), "r"(bf[nt][1]));
                }
            }
        }
    }

    int mrow0 = m0 + wm * 64;
    #pragma unroll
    for (int mt = 0; mt < 4; mt++) {
        #pragma unroll
        for (int half_ = 0; half_ < 2; half_++) {
            int m = mrow0 + mt * 16 + lr + half_ * 8;
            if (m >= Nrows) continue;
            #pragma unroll
            for (int nt = 0; nt < 2; nt++) {
                int n = n0 + wn * 16 + nt * 8 + 2 * lc;
                float b0v, b1v;
                if (MODE == 0) { b0v = bias[n]; b1v = bias[n + 1]; }
                else { b0v = (n >= 192) ? bias[n - 192] : 0.f; b1v = (n + 1 >= 192) ? bias[n + 1 - 192] : 0.f; }
                float v0 = acc[mt][nt][half_ * 2 + 0] + b0v;
                float v1 = acc[mt][nt][half_ * 2 + 1] + b1v;
                if (MODE == 0) {
                    v0 = (v0 > 0.f) ? v0 : expm1f(v0);
                    v1 = (v1 > 0.f) ? v1 : expm1f(v1);
                }
                *(__half2*)(out + (size_t)m * O + n) = __floats2half2_rn(v0, v1);
            }
        }
    }
}

// ---------------- pooling (both branches, count fused; batch sorted) ----------------
__global__ void pool_c(const __half* __restrict__ x3a, const int* __restrict__ ba,
                       float* __restrict__ pa, float* __restrict__ ca, int N0, int blocks0,
                       const __half* __restrict__ x3b, const int* __restrict__ bb,
                       float* __restrict__ pb, float* __restrict__ cb, int N1) {
    const __half* x3; const int* batch; float* pool; float* cnt; int N, blk;
    if ((int)blockIdx.x < blocks0) { x3 = x3a; batch = ba; pool = pa; cnt = ca; N = N0; blk = blockIdx.x; }
    else { x3 = x3b; batch = bb; pool = pb; cnt = cb; N = N1; blk = blockIdx.x - blocks0; }
    int t = threadIdx.x;   // 0..191
    int r0 = blk * 256;
    int rend = r0 + 256; if (rend > N) rend = N;
    if (r0 >= N) return;
    int cur = batch[r0];
    float acc = 0.f, cacc = 0.f;
    for (int i = r0; i < rend; i++) {
        int b = batch[i];
        if (b != cur) {
            atomicAdd(&pool[cur * 192 + t], acc);
            if (t == 0) atomicAdd(&cnt[cur], cacc);
            acc = 0.f; cacc = 0.f; cur = b;
        }
        float v = __half2float(x3[(size_t)i * 384 + 192 + t]);
        v = (v > 0.f) ? v : expm1f(v);
        acc += v; cacc += 1.f;
    }
    atomicAdd(&pool[cur * 192 + t], acc);
    if (t == 0) atomicAdd(&cnt[cur], cacc);
}

// ---------------- final MLP: 8 blocks (one per batch row), 448->600->256->64 ----------------
__global__ void mlp_k8(const float* __restrict__ point,
                       const float* __restrict__ l1W, const float* __restrict__ l1b,
                       const float* __restrict__ l2W, const float* __restrict__ l2b,
                       const float* __restrict__ l3W, const float* __restrict__ l3b,
                       const float* __restrict__ pool, const float* __restrict__ cnt,
                       float* __restrict__ out) {
    __shared__ float in[448];
    __shared__ float h1[600];
    __shared__ float h2[256];
    int r = blockIdx.x;
    int t = threadIdx.x;

    for (int f = t; f < 448; f += blockDim.x) {
        float v;
        if (f < 192)       v = pool[r * 192 + f] / fmaxf(cnt[r], 1.f);
        else if (f < 384)  v = pool[1536 + r * 192 + (f - 192)] / fmaxf(cnt[8 + r], 1.f);
        else               v = point[r * 64 + (f - 384)];
        in[f] = v;
    }
    __syncthreads();

    if (t < 600) {
        float acc = l1b[t];
        const float4* w = (const float4*)(l1W + t * 448);
        #pragma unroll 4
        for (int f = 0; f < 112; f++) {
            float4 wv = w[f];
            const float4 iv = *(const float4*)&in[f * 4];
            acc += wv.x * iv.x + wv.y * iv.y + wv.z * iv.z + wv.w * iv.w;
        }
        h1[t] = fmaxf(acc, 0.f);
    }
    __syncthreads();

    if (t < 256) {
        float acc = l2b[t];
        const float4* w = (const float4*)(l2W + t * 600);
        #pragma unroll 4
        for (int f = 0; f < 150; f++) {
            float4 wv = w[f];
            const float4 iv = *(const float4*)&h1[f * 4];
            acc += wv.x * iv.x + wv.y * iv.y + wv.z * iv.z + wv.w * iv.w;
        }
        h2[t] = fmaxf(acc, 0.f);
    }
    __syncthreads();

    if (t < 64) {
        float acc = l3b[t];
        const float4* w = (const float4*)(l3W + t * 256);
        #pragma unroll 4
        for (int f = 0; f < 64; f++) {
            float4 wv = w[f];
            const float4 iv = *(const float4*)&h2[f * 4];
            acc += wv.x * iv.x + wv.y * iv.y + wv.z * iv.z + wv.w * iv.w;
        }
        out[r * 64 + t] = acc;
    }
}

extern "C" void kernel_launch(void* const* d_in, const int* in_sizes, int n_in,
                              void* d_out, int out_size) {
    float* scratch = nullptr;
    cudaGetSymbolAddress((void**)&scratch, d_scratch);
    cudaFuncSetAttribute(gemm_h<64, 128, 128, 0>, cudaFuncAttributeMaxDynamicSharedMemorySize, 65536);
    cudaFuncSetAttribute(gemm_h<128, 256, 256, 0>, cudaFuncAttributeMaxDynamicSharedMemorySize, 65536);
    cudaFuncSetAttribute(gemm_h<256, 256, 384, 1>, cudaFuncAttributeMaxDynamicSharedMemorySize, 65536);

    // Resolve input ordering (dict order vs reference-signature order)
    int GX, SX, PT, GEI, GB, SEI, SB, GW, SW, LW;
    if (n_in >= 4 && in_sizes[3] == 2 * EG) {
        GX = 0; SX = 1; PT = 2; GEI = 3; GB = 4; SEI = 5; SB = 6;
        GW = 7; SW = 16; LW = 25;
    } else {
        GX = 0; SX = 1; PT = 2; GW = 3; SW = 12; LW = 21;
        GEI = 27; GB = 28; SEI = 29; SB = 30;
    }

    const float* x0g = (const float*)d_in[GX];
    const float* x0s = (const float*)d_in[SX];
    const int* eig = (const int*)d_in[GEI];
    const int* eis = (const int*)d_in[SEI];
    const int* bag = (const int*)d_in[GB];
    const int* bas = (const int*)d_in[SB];

    __half* h0g  = (__half*)(scratch + H0_G);   __half* h0s  = (__half*)(scratch + H0_S);
    __half* aggg = (__half*)(scratch + AGG_G);  __half* aggs = (__half*)(scratch + AGG_S);
    __half* x1g  = (__half*)(scratch + X1_G);   __half* x1s  = (__half*)(scratch + X1_S);
    __half* x2g  = (__half*)(scratch + X2_G);   __half* x2s  = (__half*)(scratch + X2_S);
    __half* x3g  = (__half*)(scratch + X3_G);   __half* x3s  = (__half*)(scratch + X3_S);
    float* pool = scratch + POOL;
    float* cnt  = scratch + CNTO;
    int* degg = (int*)(scratch + DEG_G);   int* degs = (int*)(scratch + DEG_S);
    int* ptrg = (int*)(scratch + PTR_G);   int* ptrs = (int*)(scratch + PTR_S);
    int* filg = (int*)(scratch + FILL_G);  int* fils = (int*)(scratch + FILL_S);
    int* ssg  = (int*)(scratch + SS_G);    int* sss  = (int*)(scratch + SS_S);
    int* bsg  = (int*)(scratch + BS_G);    int* bss  = (int*)(scratch + BS_S);

    int b0 = (NG + 127) / 128, b1 = (NS + 127) / 128;
    int nbg = (NG + 255) / 256, nbs = (NS + 255) / 256;

    // ---- init: zero(pool+cnt+deg) + fp16 convert of both inputs, one launch ----
    {
        int nz4 = 15777;
        int n2a = NG * 32, n2b = NS * 32;
        int tot = nz4 + n2a + n2b;
        init_k<<<(tot + 255) / 256, 256>>>(scratch + POOL, nz4, x0g, h0g, n2a, x0s, h0s, n2b);
    }

    // ---- build CSR (once; shared by all three layers) ----
    {
        int tot = EG + ES;
        hist_c<<<(tot + 255) / 256, 256>>>(eig, EG, degg, eis, ES, degs);
        scan_blk<<<nbg + nbs, 256>>>(degg, ptrg, bsg, NG, nbg, degs, ptrs, bss, NS);
        scan_fin<<<(NG + NS + 2 + 255) / 256, 256>>>(ptrg, filg, bsg, NG, nbg,
                                                     ptrs, fils, bss, NS, nbs);
        fill_c<<<(tot + 255) / 256, 256>>>(eig, EG, filg, ssg, eis, ES, fils, sss);
    }

    // ---- layer 1: c=64 -> o=128, K=128
    {
        int tot = (NG + NS) * 8;
        gather_h<64, 3><<<(tot + 255) / 256, 256>>>(h0g, ptrg, ssg, aggg, NG,
                                                    h0s, ptrs, sss, aggs, NS);
        size_t smem = (size_t)(64 * 136 + 2 * 128 * 40) * 2;
        gemm_h<64, 128, 128, 0><<<dim3(2, b0 + b1), 256, smem>>>(
            aggg, h0g, (const float*)d_in[GW + 0], (const float*)d_in[GW + 1],
            (const float*)d_in[GW + 2], x1g, NG,
            aggs, h0s, (const float*)d_in[SW + 0], (const float*)d_in[SW + 1],
            (const float*)d_in[SW + 2], x1s, NS, b0);
    }
    // ---- layer 2: c=128 -> o=256, K=256
    {
        int tot = (NG + NS) * 16;
        gather_h<128, 4><<<(tot + 255) / 256, 256>>>(x1g, ptrg, ssg, aggg, NG,
                                                     x1s, ptrs, sss, aggs, NS);
        size_t smem = (size_t)(64 * 264 + 2 * 128 * 40) * 2;
        gemm_h<128, 256, 256, 0><<<dim3(4, b0 + b1), 256, smem>>>(
            aggg, x1g, (const float*)d_in[GW + 3], (const float*)d_in[GW + 4],
            (const float*)d_in[GW + 5], x2g, NG,
            aggs, x1s, (const float*)d_in[SW + 3], (const float*)d_in[SW + 4],
            (const float*)d_in[SW + 5], x2s, NS, b0);
    }
    // ---- layer 3: GEMM first (linearity swap), then width-192 CSR gather, then pool
    {
        size_t smem = (size_t)(64 * 264 + 2 * 128 * 40) * 2;
        gemm_h<256, 256, 384, 1><<<dim3(6, b0 + b1), 256, smem>>>(
            x2g, x2g, (const float*)d_in[GW + 6], (const float*)d_in[GW + 7],
            (const float*)d_in[GW + 8], x3g, NG,
            x2s, x2s, (const float*)d_in[SW + 6], (const float*)d_in[SW + 7],
            (const float*)d_in[SW + 8], x3s, NS, b0);
        int tot = (NG + NS) * 8;
        gather3_h<<<(tot + 255) / 256, 256>>>(ptrg, ssg, x3g, NG, ptrs, sss, x3s, NS);
        int pb0 = (NG + 255) / 256, pb1 = (NS + 255) / 256;
        pool_c<<<pb0 + pb1, 192>>>(x3g, bag, pool, cnt, NG, pb0,
                                   x3s, bas, pool + 1536, cnt + 8, NS);
    }

    mlp_k8<<<8, 640>>>((const float*)d_in[PT],
                       (const float*)d_in[LW + 0], (const float*)d_in[LW + 1],
                       (const float*)d_in[LW + 2], (const float*)d_in[LW + 3],
                       (const float*)d_in[LW + 4], (const float*)d_in[LW + 5],
                       pool, cnt, (float*)d_out);
}